// round 7
// baseline (speedup 1.0000x reference)
#include <cuda_runtime.h>

// Problem constants
#define Bsz 128
#define Cch 64
#define Hh  32
#define Tt  256
#define BG  16   // batches per block
#define IP  2    // hidden rows per thread
#define NG  16   // i-groups per (dir,b)  (NG*IP = Hh)
// threads = 2 dirs * BG * NG = 2*16*16 = 512  (16 warps, 4 per SMSP)

typedef unsigned long long u64;

__device__ __forceinline__ u64 ffma2(u64 a, u64 b, u64 c) {
    u64 d;
    asm("fma.rn.f32x2 %0, %1, %2, %3;" : "=l"(d) : "l"(a), "l"(b), "l"(c));
    return d;
}
__device__ __forceinline__ u64 pack2(float lo, float hi) {
    u64 r;
    asm("mov.b64 %0, {%1, %2};" : "=l"(r) : "f"(lo), "f"(hi));
    return r;
}
__device__ __forceinline__ void unpack2(u64 v, float& lo, float& hi) {
    asm("mov.b64 {%0, %1}, %2;" : "=f"(lo), "=f"(hi) : "l"(v));
}

__global__ __launch_bounds__(512, 1)
void mrnn_kernel(const float* __restrict__ x,  const float* __restrict__ m,
                 const float* __restrict__ dd,
                 const float* __restrict__ Wf, const float* __restrict__ Vf,
                 const float* __restrict__ cf,
                 const float* __restrict__ Wb, const float* __restrict__ Vb,
                 const float* __restrict__ cb,
                 const float* __restrict__ U,  const float* __restrict__ c0,
                 float* __restrict__ out)
{
    // h state, double buffered: [buf][dir][b][40]  (stride 40 floats => the 2
    // batch-rows inside a warp land on disjoint bank spans, broadcast LDS.128)
    __shared__ __align__(16) float hbuf[2 * 2 * BG * 40];   // 10240 B
    // per-direction projection contributions: [dir][b][t]
    __shared__ float sfb[2 * BG * Tt];                       // 32768 B

    const int tid = threadIdx.x;
    const int g   = tid & 15;         // i-group (16 per (dir,b)) - intra-warp
    const int b   = (tid >> 4) & 15;  // local batch
    const int dir = tid >> 8;         // 0 = forward, 1 = backward
    const int c   = blockIdx.y;
    const int b0  = blockIdx.x * BG;
    const int i0  = g * IP;

    // ---- preload per-thread weights into registers ----
    const float* Wg = (dir ? Wb : Wf) + c * Hh * Hh;
    const float* Vg = (dir ? Vb : Vf) + c * Hh * 3;
    const float* cg = (dir ? cb : cf) + c * Hh;

    u64   w[IP][16];                 // W rows, packed as (k even, k odd) pairs
    float v0[IP], v1[IP], v2[IP], cbi[IP], uu[IP];
    #pragma unroll
    for (int i = 0; i < IP; i++) {
        const u64* wr = (const u64*)(Wg + (i0 + i) * Hh);
        #pragma unroll
        for (int j = 0; j < 16; j++) w[i][j] = __ldg(wr + j);
        v0[i]  = __ldg(Vg + (i0 + i) * 3 + 0);
        v1[i]  = __ldg(Vg + (i0 + i) * 3 + 1);
        v2[i]  = __ldg(Vg + (i0 + i) * 3 + 2);
        cbi[i] = __ldg(cg + i0 + i);
        uu[i]  = __ldg(U + c * 2 * Hh + dir * Hh + i0 + i);
    }

    const long bc = (long)(b0 + b) * Cch * Tt + (long)c * Tt;
    const float* xp = x  + bc;
    const float* mp = m  + bc;
    const float* dp = dd + bc;

    const int hrow0 = (dir * BG + b) * 40;             // buffer 0
    const int hrow1 = (2 * BG + dir * BG + b) * 40;    // buffer 1
    float* srow = &sfb[(dir * BG + b) * Tt];

    // zero own h rows (h0 = 0); intra-warp visibility only
    *(float2*)(&hbuf[hrow0 + i0]) = make_float2(0.f, 0.f);
    *(float2*)(&hbuf[hrow1 + i0]) = make_float2(0.f, 0.f);
    __syncwarp();

    // input for step n reads padded index: q = max(n-1,0), tt = dir ? T-1-q : q
    const int tt0 = dir ? (Tt - 1) : 0;
    float vx = __ldg(xp + tt0);
    float vm = __ldg(mp + tt0);
    float vd = __ldg(dp + tt0);

    // ---- T sequential RNN steps (warp-independent: no block barrier) ----
    #pragma unroll 2
    for (int n = 0; n < Tt; n++) {
        // prefetch inputs for step n+1 (q_next = n; clamps naturally at n=T-1)
        const int ttn = dir ? (Tt - 1 - n) : n;
        const float nvx = __ldg(xp + ttn);
        const float nvm = __ldg(mp + ttn);
        const float nvd = __ldg(dp + ttn);

        const ulonglong2* hr = (const ulonglong2*)&hbuf[(n & 1) ? hrow1 : hrow0];
        float*            hw = &hbuf[(n & 1) ? hrow0 : hrow1];

        // acc lane-lo seeded with bias + V*v; lane-hi accumulates odd-k terms
        u64 acc[IP];
        #pragma unroll
        for (int i = 0; i < IP; i++)
            acc[i] = pack2(fmaf(v2[i], vd, fmaf(v1[i], vm, fmaf(v0[i], vx, cbi[i]))), 0.f);

        // 32x32 matvec slice: 8 broadcast LDS.128 + 32 packed FMA2 (64 MACs)
        #pragma unroll
        for (int j = 0; j < 8; j++) {
            const ulonglong2 hp = hr[j];
            #pragma unroll
            for (int i = 0; i < IP; i++) {
                acc[i] = ffma2(w[i][2 * j],     hp.x, acc[i]);
                acc[i] = ffma2(w[i][2 * j + 1], hp.y, acc[i]);
            }
        }

        float hn[IP];
        float s = 0.f;
        #pragma unroll
        for (int i = 0; i < IP; i++) {
            float lo, hi; unpack2(acc[i], lo, hi);
            hn[i] = fmaxf(lo + hi, 0.f);
            s = fmaf(uu[i], hn[i], s);          // fused U projection
        }

        *(float2*)(hw + i0) = make_float2(hn[0], hn[1]);

        // reduce projection over the 16 i-groups of this (dir, b)
        s += __shfl_xor_sync(0xffffffffu, s, 1, 16);
        s += __shfl_xor_sync(0xffffffffu, s, 2, 16);
        s += __shfl_xor_sync(0xffffffffu, s, 4, 16);
        s += __shfl_xor_sync(0xffffffffu, s, 8, 16);
        const int tout = dir ? (Tt - 1 - n) : n;
        if (g == 0) srow[tout] = s;

        vx = nvx; vm = nvm; vd = nvd;
        __syncwarp();   // order hbuf STS before next step's LDS (intra-warp)
    }

    __syncthreads();    // single block barrier: fwd+bwd sfb both complete

    // ---- combine fwd + bwd contributions, final relu, coalesced store ----
    const float c0c = __ldg(c0 + c);
    for (int idx = tid; idx < BG * Tt; idx += 512) {
        const int bb = idx >> 8;     // local batch
        const int t  = idx & 255;
        const float v = fmaxf(sfb[bb * Tt + t] + sfb[(BG + bb) * Tt + t] + c0c, 0.f);
        out[(long)(b0 + bb) * Cch * Tt + (long)c * Tt + t] = v;
    }
}

extern "C" void kernel_launch(void* const* d_in, const int* in_sizes, int n_in,
                              void* d_out, int out_size)
{
    const float* x  = (const float*)d_in[0];
    const float* m  = (const float*)d_in[1];
    const float* d  = (const float*)d_in[2];
    const float* Wf = (const float*)d_in[3];
    const float* Vf = (const float*)d_in[4];
    const float* cf = (const float*)d_in[5];
    const float* Wb = (const float*)d_in[6];
    const float* Vb = (const float*)d_in[7];
    const float* cb = (const float*)d_in[8];
    const float* U  = (const float*)d_in[9];
    const float* c0 = (const float*)d_in[10];

    dim3 grid(Bsz / BG, Cch);   // 8 x 64 = 512 blocks
    mrnn_kernel<<<grid, 512>>>(x, m, d, Wf, Vf, cf, Wb, Vb, cb, U, c0,
                               (float*)d_out);
}

// round 8
// speedup vs baseline: 1.4234x; 1.4234x over previous
#include <cuda_runtime.h>

// Problem constants
#define Bsz 128
#define Cch 64
#define Hh  32
#define Tt  256
#define BG  8    // batches per block
#define IP  4    // hidden rows per thread
// threads = 2 dirs * BG * (Hh/IP) = 2*8*8 = 128 (4 warps); 2 CTAs co-resident/SM

typedef unsigned long long u64;

__device__ __forceinline__ u64 ffma2(u64 a, u64 b, u64 c) {
    u64 d;
    asm("fma.rn.f32x2 %0, %1, %2, %3;" : "=l"(d) : "l"(a), "l"(b), "l"(c));
    return d;
}
__device__ __forceinline__ u64 pack2(float lo, float hi) {
    u64 r;
    asm("mov.b64 %0, {%1, %2};" : "=l"(r) : "f"(lo), "f"(hi));
    return r;
}
__device__ __forceinline__ void unpack2(u64 v, float& lo, float& hi) {
    asm("mov.b64 {%0, %1}, %2;" : "=f"(lo), "=f"(hi) : "l"(v));
}

__global__ __launch_bounds__(128, 2)
void mrnn_kernel(const float* __restrict__ x,  const float* __restrict__ m,
                 const float* __restrict__ dd,
                 const float* __restrict__ Wf, const float* __restrict__ Vf,
                 const float* __restrict__ cf,
                 const float* __restrict__ Wb, const float* __restrict__ Vb,
                 const float* __restrict__ cb,
                 const float* __restrict__ U,  const float* __restrict__ c0,
                 float* __restrict__ out)
{
    // h state, double buffered: [buf][dir][b][40]  (stride 40 floats => the 4
    // batch-rows inside a warp land on disjoint bank spans, broadcast LDS.128)
    __shared__ __align__(16) float hbuf[2 * 2 * BG * 40];   // 5120 B
    // per-direction projection contributions: [dir][b][t]
    __shared__ float sfb[2 * BG * Tt];                       // 16384 B

    const int tid = threadIdx.x;
    const int g   = tid & 7;          // i-group (8 per (dir,b)) - intra-warp
    const int b   = (tid >> 3) & 7;   // local batch
    const int dir = tid >> 6;         // 0 = forward (warps 0-1), 1 = backward
    const int c   = blockIdx.y;
    const int b0  = blockIdx.x * BG;
    const int i0  = g * IP;

    // ---- preload per-thread weights into registers ----
    const float* Wg = (dir ? Wb : Wf) + c * Hh * Hh;
    const float* Vg = (dir ? Vb : Vf) + c * Hh * 3;
    const float* cg = (dir ? cb : cf) + c * Hh;

    u64   w[IP][16];                 // W rows, packed as (k even, k odd) pairs
    float v0[IP], v1[IP], v2[IP], cbi[IP], uu[IP];
    #pragma unroll
    for (int i = 0; i < IP; i++) {
        const u64* wr = (const u64*)(Wg + (i0 + i) * Hh);
        #pragma unroll
        for (int j = 0; j < 16; j++) w[i][j] = __ldg(wr + j);
        v0[i]  = __ldg(Vg + (i0 + i) * 3 + 0);
        v1[i]  = __ldg(Vg + (i0 + i) * 3 + 1);
        v2[i]  = __ldg(Vg + (i0 + i) * 3 + 2);
        cbi[i] = __ldg(cg + i0 + i);
        uu[i]  = __ldg(U + c * 2 * Hh + dir * Hh + i0 + i);
    }

    const long bc = (long)(b0 + b) * Cch * Tt + (long)c * Tt;
    const float* xp = x  + bc;
    const float* mp = m  + bc;
    const float* dp = dd + bc;

    const int hrow0 = (dir * BG + b) * 40;             // buffer 0
    const int hrow1 = (2 * BG + dir * BG + b) * 40;    // buffer 1
    float* srow = &sfb[(dir * BG + b) * Tt];

    // zero own h rows (h0 = 0); intra-warp visibility only
    *(float4*)(&hbuf[hrow0 + i0]) = make_float4(0.f, 0.f, 0.f, 0.f);
    *(float4*)(&hbuf[hrow1 + i0]) = make_float4(0.f, 0.f, 0.f, 0.f);
    __syncwarp();

    // input for step n reads padded index: q = max(n-1,0), tt = dir ? T-1-q : q
    const int tt0 = dir ? (Tt - 1) : 0;
    float vx = __ldg(xp + tt0);
    float vm = __ldg(mp + tt0);
    float vd = __ldg(dp + tt0);

    float sprev = 0.f;   // deferred projection value from previous step
    int   tprev = 0;

    // ---- T sequential RNN steps (warp-independent: no block barrier) ----
    #pragma unroll 2
    for (int n = 0; n < Tt; n++) {
        // prefetch inputs for step n+1 (q_next = n; clamps naturally at n=T-1)
        // NOTE: ttn also equals this step's output time index tout.
        const int ttn = dir ? (Tt - 1 - n) : n;
        const float nvx = __ldg(xp + ttn);
        const float nvm = __ldg(mp + ttn);
        const float nvd = __ldg(dp + ttn);

        const ulonglong2* hr = (const ulonglong2*)&hbuf[(n & 1) ? hrow1 : hrow0];
        float*            hw = &hbuf[(n & 1) ? hrow0 : hrow1];

        // acc lane-lo seeded with bias + V*v; lane-hi accumulates odd-k terms
        u64 acc[IP];
        #pragma unroll
        for (int i = 0; i < IP; i++)
            acc[i] = pack2(fmaf(v2[i], vd, fmaf(v1[i], vm, fmaf(v0[i], vx, cbi[i]))), 0.f);

        // 32x32 matvec: 8 broadcast LDS.128 + 64 packed FMA2 (128 MACs)
        #pragma unroll
        for (int j = 0; j < 8; j++) {
            const ulonglong2 hp = hr[j];
            #pragma unroll
            for (int i = 0; i < IP; i++) {
                acc[i] = ffma2(w[i][2 * j],     hp.x, acc[i]);
                acc[i] = ffma2(w[i][2 * j + 1], hp.y, acc[i]);
            }
        }

        float hn[IP];
        float s = 0.f;
        #pragma unroll
        for (int i = 0; i < IP; i++) {
            float lo, hi; unpack2(acc[i], lo, hi);
            hn[i] = fmaxf(lo + hi, 0.f);
            s = fmaf(uu[i], hn[i], s);          // fused U projection
        }

        *(float4*)(hw + i0) = make_float4(hn[0], hn[1], hn[2], hn[3]);

        __syncwarp();   // order hbuf STS before next step's LDS (intra-warp)

        // DEFERRED reduce of previous step's projection: its 3-shfl chain now
        // overlaps the next step's LDS/FMA stream instead of sitting on the
        // recurrence critical path.
        if (n) {
            float r = sprev;
            r += __shfl_xor_sync(0xffffffffu, r, 1, 8);
            r += __shfl_xor_sync(0xffffffffu, r, 2, 8);
            r += __shfl_xor_sync(0xffffffffu, r, 4, 8);
            if (g == 0) srow[tprev] = r;
        }
        sprev = s; tprev = ttn;

        vx = nvx; vm = nvm; vd = nvd;
    }

    // tail: reduce + store the final step's projection
    {
        float r = sprev;
        r += __shfl_xor_sync(0xffffffffu, r, 1, 8);
        r += __shfl_xor_sync(0xffffffffu, r, 2, 8);
        r += __shfl_xor_sync(0xffffffffu, r, 4, 8);
        if (g == 0) srow[tprev] = r;
    }

    __syncthreads();    // single block barrier: fwd+bwd sfb both complete

    // ---- combine fwd + bwd contributions, final relu, coalesced store ----
    const float c0c = __ldg(c0 + c);
    for (int idx = tid; idx < BG * Tt; idx += 128) {
        const int bb = idx >> 8;     // local batch
        const int t  = idx & 255;
        const float v = fmaxf(sfb[bb * Tt + t] + sfb[(BG + bb) * Tt + t] + c0c, 0.f);
        out[(long)(b0 + bb) * Cch * Tt + (long)c * Tt + t] = v;
    }
}

extern "C" void kernel_launch(void* const* d_in, const int* in_sizes, int n_in,
                              void* d_out, int out_size)
{
    const float* x  = (const float*)d_in[0];
    const float* m  = (const float*)d_in[1];
    const float* d  = (const float*)d_in[2];
    const float* Wf = (const float*)d_in[3];
    const float* Vf = (const float*)d_in[4];
    const float* cf = (const float*)d_in[5];
    const float* Wb = (const float*)d_in[6];
    const float* Vb = (const float*)d_in[7];
    const float* cb = (const float*)d_in[8];
    const float* U  = (const float*)d_in[9];
    const float* c0 = (const float*)d_in[10];

    dim3 grid(Bsz / BG, Cch);   // 16 x 64 = 1024 blocks
    mrnn_kernel<<<grid, 128>>>(x, m, d, Wf, Vf, cf, Wb, Vb, cb, U, c0,
                               (float*)d_out);
}